// round 2
// baseline (speedup 1.0000x reference)
#include <cuda_runtime.h>

#define BB 32
#define LL 4096
#define CC 7
#define NK 74
#define TL 128
#define SX 152          // >= TL+23 entries, even for 8B row alignment
#define NCOL 512

__device__ __forceinline__ unsigned long long fma2(unsigned long long a,
                                                   unsigned long long b,
                                                   unsigned long long c) {
    unsigned long long d;
    asm("fma.rn.f32x2 %0, %1, %2, %3;" : "=l"(d) : "l"(a), "l"(b), "l"(c));
    return d;
}

__device__ __forceinline__ unsigned long long packdup(float w) {
    unsigned long long d;
    asm("mov.b64 %0, {%1, %2};" : "=l"(d) : "f"(w), "f"(w));
    return d;
}

__device__ __forceinline__ void unpack2(unsigned long long v, float& lo, float& hi) {
    asm("mov.b64 {%0, %1}, %2;" : "=f"(lo), "=f"(hi) : "l"(v));
}

__global__ __launch_bounds__(NCOL, 1)
void rocket_conv_kernel(const float* __restrict__ x,
                        const float* __restrict__ kern,
                        float* __restrict__ out) {
    __shared__ __align__(16) float ks[NK * 24];      // 74*24 weights
    __shared__ __align__(16) float xsA[CC][SX];      // x-hat window
    __shared__ __align__(16) float xsB[CC][SX];      // shifted by +1 copy

    const int b   = blockIdx.y;
    const int l0  = blockIdx.x * TL;
    const int tid = threadIdx.x;

    // ---- stage kernels into SMEM ----
    for (int i = tid; i < NK * 24; i += NCOL) ks[i] = kern[i];

    // ---- stage x window [l0-22 .. l0+TL] with zero extension ----
    const int NLOAD = (TL + 23) * CC;
    for (int i = tid; i < NLOAD; i += NCOL) {
        int t = i / CC, c = i % CC;
        int g = l0 - 22 + t;
        float v = (g >= 0 && g < LL) ? x[(b * LL + g) * CC + c] : 0.0f;
        xsA[c][t] = v;
        if (t >= 1) xsB[c][t - 1] = v;
    }
    __syncthreads();

    // ---- per-thread column mapping ----
    const int col = tid;
    const int c = (col < 511) ? (col / 73) : 0;
    const int k = (col < 511) ? (col % 73) : 73;

    // Dense 24-tap filter: W[m] corresponds to offset o = m-22,
    // W[m] = kernels[k, 7 - m/3, m%3]  ->  flat k*24 + 21 - 3*(m/3) + m%3
    unsigned long long Wp[24];
    #pragma unroll
    for (int m = 0; m < 24; m++) {
        float w = ks[k * 24 + 21 - 3 * (m / 3) + (m % 3)];
        Wp[m] = packdup(w);
    }

    const float* rowA = xsA[c];
    const float* rowB = xsB[c];
    float* outp = out + ((size_t)(b * LL + l0)) * NCOL + col;

    #pragma unroll 1
    for (int lt = 0; lt < TL; lt += 4) {
        unsigned long long a01 = 0ull, a23 = 0ull;
        // pair at index p: (xhat[p], xhat[p+1]); p even -> xsA[p], p odd -> xsB[p-1]
        unsigned long long q0 = *reinterpret_cast<const unsigned long long*>(rowA + lt);      // p = lt   (even)
        unsigned long long q1 = *reinterpret_cast<const unsigned long long*>(rowB + lt);      // p = lt+1 (odd)
        #pragma unroll
        for (int m = 0; m < 24; m++) {
            unsigned long long q2;
            if (((m + 2) & 1) == 0)
                q2 = *reinterpret_cast<const unsigned long long*>(rowA + lt + m + 2);
            else
                q2 = *reinterpret_cast<const unsigned long long*>(rowB + lt + m + 1);
            a01 = fma2(Wp[m], q0, a01);   // outputs l0+lt, l0+lt+1
            a23 = fma2(Wp[m], q2, a23);   // outputs l0+lt+2, l0+lt+3
            q0 = q1; q1 = q2;
        }
        float o0, o1, o2, o3;
        unpack2(a01, o0, o1);
        unpack2(a23, o2, o3);
        outp[(size_t)(lt + 0) * NCOL] = o0;
        outp[(size_t)(lt + 1) * NCOL] = o1;
        outp[(size_t)(lt + 2) * NCOL] = o2;
        outp[(size_t)(lt + 3) * NCOL] = o3;
    }

    // ---- fix l = L-1: the j=2 taps read the zero-padded win[:, L] row ----
    if (l0 + TL == LL) {
        float s = 0.0f;
        #pragma unroll
        for (int i = 0; i < 8; i++) {
            #pragma unroll
            for (int j = 0; j < 2; j++) {
                // tap index s_idx = L-2+j-3i -> local TL+20+j-3i (always valid)
                s += ks[k * 24 + i * 3 + j] * rowA[TL + 20 + j - 3 * i];
            }
        }
        out[((size_t)(b * LL + LL - 1)) * NCOL + col] = s;
    }
}

extern "C" void kernel_launch(void* const* d_in, const int* in_sizes, int n_in,
                              void* d_out, int out_size) {
    const float* x    = (const float*)d_in[0];
    const float* kern = (const float*)d_in[1];
    float* out        = (float*)d_out;
    dim3 grid(LL / TL, BB);
    rocket_conv_kernel<<<grid, NCOL>>>(x, kern, out);
}

// round 4
// speedup vs baseline: 1.2869x; 1.2869x over previous
#include <cuda_runtime.h>

#define BB 32
#define LL 4096
#define CC 7
#define NK 74
#define TL 128
#define SX 156          // multiple of 4 (16B row alignment), >= TL+32 headroom for LDS.128
#define NCOL 512

typedef unsigned long long u64;

__device__ __forceinline__ u64 fma2(u64 a, u64 b, u64 c) {
    u64 d;
    asm("fma.rn.f32x2 %0, %1, %2, %3;" : "=l"(d) : "l"(a), "l"(b), "l"(c));
    return d;
}

__device__ __forceinline__ u64 packdup(float w) {
    u64 d;
    asm("mov.b64 %0, {%1, %2};" : "=l"(d) : "f"(w), "f"(w));
    return d;
}

__device__ __forceinline__ void unpack2(u64 v, float& lo, float& hi) {
    asm("mov.b64 {%0, %1}, %2;" : "=f"(lo), "=f"(hi) : "l"(v));
}

// One pass over 12 taps (even-m or odd-m half of the 24-tap filter).
// base points at the row copy where pair(p) = base[off], off = p (even copy)
// or p-1 (odd copy). Chunk j = base[4j..4j+3] (16B aligned), holding pairs
// at offsets 4j (lo) and 4j+2 (hi). Outer step j covers taps m=4j and m=4j+2
// of this pass's tap sequence.
__device__ __forceinline__ void pass12(const float* __restrict__ base,
                                       const u64* __restrict__ W,  // 12 taps
                                       u64& a0, u64& a1, u64& a2, u64& a3) {
    ulonglong2 c0 = *reinterpret_cast<const ulonglong2*>(base);
    ulonglong2 c1 = *reinterpret_cast<const ulonglong2*>(base + 4);
    #pragma unroll
    for (int j = 0; j < 6; j++) {
        ulonglong2 c2 = *reinterpret_cast<const ulonglong2*>(base + 4 * j + 8);
        u64 w1 = W[2 * j];         // tap offset 4j
        a0 = fma2(w1, c0.x, a0);
        a1 = fma2(w1, c0.y, a1);
        a2 = fma2(w1, c1.x, a2);
        a3 = fma2(w1, c1.y, a3);
        u64 w2 = W[2 * j + 1];     // tap offset 4j+2
        a0 = fma2(w2, c0.y, a0);
        a1 = fma2(w2, c1.x, a1);
        a2 = fma2(w2, c1.y, a2);
        a3 = fma2(w2, c2.x, a3);
        c0 = c1;
        c1 = c2;
    }
}

__global__ __launch_bounds__(NCOL, 1)
void rocket_conv_kernel(const float* __restrict__ x,
                        const float* __restrict__ kern,
                        float* __restrict__ out) {
    __shared__ __align__(16) float ks[NK * 24];
    __shared__ __align__(16) float xsA[CC][SX];   // xhat[t]   (even-offset pairs)
    __shared__ __align__(16) float xsB[CC][SX];   // xhat[t+1] (odd-offset pairs)

    const int b   = blockIdx.y;
    const int l0  = blockIdx.x * TL;
    const int tid = threadIdx.x;

    // ---- stage kernels ----
    for (int i = tid; i < NK * 24; i += NCOL) ks[i] = kern[i];

    // ---- stage x window xhat[t] = x[l0-22+t], zero-extended, t in [0,155) ----
    const int NLOAD = 155 * CC;
    for (int i = tid; i < NLOAD; i += NCOL) {
        int t = i / CC, c = i % CC;
        int g = l0 - 22 + t;
        float v = (g >= 0 && g < LL) ? x[(b * LL + g) * CC + c] : 0.0f;
        xsA[c][t] = v;
        if (t >= 1) xsB[c][t - 1] = v;
    }
    __syncthreads();

    // ---- per-thread column mapping ----
    const int col = tid;
    const int c = (col < 511) ? (col / 73) : 0;
    const int k = (col < 511) ? (col % 73) : 73;

    // Dense 24-tap filter: tap m (offset o = m-22):
    //   W[m] = kernels[k, 7 - m/3, m%3] -> flat k*24 + 21 - 3*(m/3) + m%3
    // Split into even/odd halves, duplicated for f32x2.
    u64 We[12], Wo[12];
    #pragma unroll
    for (int j = 0; j < 12; j++) {
        int me = 2 * j, mo = 2 * j + 1;
        We[j] = packdup(ks[k * 24 + 21 - 3 * (me / 3) + (me % 3)]);
        Wo[j] = packdup(ks[k * 24 + 21 - 3 * (mo / 3) + (mo % 3)]);
    }

    const float* rowA = xsA[c];
    const float* rowB = xsB[c];
    float* outp = out + ((size_t)(b * LL + l0)) * NCOL + col;

    #pragma unroll 1
    for (int lt = 0; lt < TL; lt += 8) {
        u64 a0 = 0ull, a1 = 0ull, a2 = 0ull, a3 = 0ull;
        // even taps read xsA (pair(p)=rowA[p], p even)
        pass12(rowA + lt, We, a0, a1, a2, a3);
        // odd taps read xsB (pair(p)=rowB[p-1], p odd -> same chunk structure)
        pass12(rowB + lt, Wo, a0, a1, a2, a3);

        float o0, o1, o2, o3, o4, o5, o6, o7;
        unpack2(a0, o0, o1);
        unpack2(a1, o2, o3);
        unpack2(a2, o4, o5);
        unpack2(a3, o6, o7);
        outp[(size_t)0 * NCOL] = o0;
        outp[(size_t)1 * NCOL] = o1;
        outp[(size_t)2 * NCOL] = o2;
        outp[(size_t)3 * NCOL] = o3;
        outp[(size_t)4 * NCOL] = o4;
        outp[(size_t)5 * NCOL] = o5;
        outp[(size_t)6 * NCOL] = o6;
        outp[(size_t)7 * NCOL] = o7;
        outp += (size_t)8 * NCOL;
    }

    // ---- fix l = L-1: reference zero-pads the whole win row at t=L, so the
    // j=2 taps vanish there (they are NOT plain x zero-extension). ----
    if (l0 + TL == LL) {
        float s = 0.0f;
        #pragma unroll
        for (int i = 0; i < 8; i++) {
            #pragma unroll
            for (int j = 0; j < 2; j++) {
                s += ks[k * 24 + i * 3 + j] * rowA[TL + 20 + j - 3 * i];
            }
        }
        out[((size_t)(b * LL + LL - 1)) * NCOL + col] = s;
    }
}

extern "C" void kernel_launch(void* const* d_in, const int* in_sizes, int n_in,
                              void* d_out, int out_size) {
    const float* x    = (const float*)d_in[0];
    const float* kern = (const float*)d_in[1];
    float* out        = (float*)d_out;
    dim3 grid(LL / TL, BB);
    rocket_conv_kernel<<<grid, NCOL>>>(x, kern, out);
}

// round 9
// speedup vs baseline: 1.4619x; 1.1360x over previous
#include <cuda_runtime.h>

#define BB 32
#define LL 4096
#define CC 7
#define NK 74
#define TL 128
#define SX 156          // multiple of 4 floats -> every row 16B aligned
#define NCOL 512

typedef unsigned long long u64;

__device__ __forceinline__ u64 fma2(u64 a, u64 b, u64 c) {
    u64 d;
    asm("fma.rn.f32x2 %0, %1, %2, %3;" : "=l"(d) : "l"(a), "l"(b), "l"(c));
    return d;
}

__device__ __forceinline__ u64 pack2(float lo, float hi) {
    u64 d;
    asm("mov.b64 %0, {%1, %2};" : "=l"(d) : "f"(lo), "f"(hi));
    return d;
}

__device__ __forceinline__ void unpack2(u64 v, float& lo, float& hi) {
    asm("mov.b64 {%0, %1}, %2;" : "=f"(lo), "=f"(hi) : "l"(v));
}

// One pass: 4 outputs at even local offsets {0,2,4,6} relative to `base`'s
// pair indexing. Pair P = (base[2P], base[2P+1]); chunk i (16B) = pairs 2i, 2i+1.
// Output t accumulates fma2(W[j], pair(t+j)) for j in [0,12).
__device__ __forceinline__ void pass_quad(const float* __restrict__ base,
                                          const u64* __restrict__ W,  // 12 tap-pairs
                                          u64 acc[4]) {
    #pragma unroll
    for (int i = 0; i < 8; i++) {
        ulonglong2 ch = *reinterpret_cast<const ulonglong2*>(base + 4 * i);
        #pragma unroll
        for (int h = 0; h < 2; h++) {
            const int P = 2 * i + h;
            u64 pr = h ? ch.y : ch.x;
            #pragma unroll
            for (int t = 0; t < 4; t++) {
                const int j = P - t;
                if (j >= 0 && j < 12) acc[t] = fma2(W[j], pr, acc[t]);
            }
        }
    }
}

__global__ __launch_bounds__(NCOL, 2)
void rocket_conv_kernel(const float* __restrict__ x,
                        const float* __restrict__ kern,
                        float* __restrict__ out) {
    __shared__ __align__(16) float ks[NK * 24];
    __shared__ __align__(16) float xsA[CC][SX];   // xhat[t]
    __shared__ __align__(16) float xsB[CC][SX];   // xhat[t+1]

    const int b   = blockIdx.y;
    const int l0  = blockIdx.x * TL;
    const int tid = threadIdx.x;

    // ---- stage kernels ----
    for (int i = tid; i < NK * 24; i += NCOL) ks[i] = kern[i];

    // ---- stage x window xhat[t] = x[b, l0-22+t], zero-extended, t in [0,155) ----
    const int NLOAD = 155 * CC;
    for (int i = tid; i < NLOAD; i += NCOL) {
        int t = i / CC, c = i % CC;
        int g = l0 - 22 + t;
        float v = (g >= 0 && g < LL) ? x[(b * LL + g) * CC + c] : 0.0f;
        xsA[c][t] = v;
        if (t >= 1) xsB[c][t - 1] = v;
    }
    __syncthreads();

    // ---- per-thread column mapping ----
    const int col = tid;
    const int c = (col < 511) ? (col / 73) : 0;
    const int k = (col < 511) ? (col % 73) : 73;

    // Dense 24-tap filter, tap m (time offset m-22):
    //   W[m] = kernels[k, 7 - m/3, m%3] -> flat k*24 + 21 - 3*(m/3) + m%3
    // Packed as adjacent-tap pairs: Wp[j] = (W[2j], W[2j+1]).
    u64 Wp[12];
    #pragma unroll
    for (int j = 0; j < 12; j++) {
        int me = 2 * j, mo = 2 * j + 1;
        float we = ks[k * 24 + 21 - 3 * (me / 3) + (me % 3)];
        float wo = ks[k * 24 + 21 - 3 * (mo / 3) + (mo % 3)];
        Wp[j] = pack2(we, wo);
    }

    const float* rowA = xsA[c];
    const float* rowB = xsB[c];
    float* outp = out + ((size_t)(b * LL + l0)) * NCOL + col;

    #pragma unroll 1
    for (int lt = 0; lt < TL; lt += 8) {
        u64 aE[4] = {0ull, 0ull, 0ull, 0ull};   // outputs lt+0,2,4,6
        u64 aO[4] = {0ull, 0ull, 0ull, 0ull};   // outputs lt+1,3,5,7
        // even offsets d=2t: pairs (xhat[lt+d+2j], xhat[lt+d+2j+1]) from rowA
        pass_quad(rowA + lt, Wp, aE);
        // odd offsets d=2t+1: same pairs shifted by one -> rowB
        pass_quad(rowB + lt, Wp, aO);

        #pragma unroll
        for (int t = 0; t < 4; t++) {
            float lo, hi;
            unpack2(aE[t], lo, hi);
            outp[(size_t)(2 * t) * NCOL] = lo + hi;
            unpack2(aO[t], lo, hi);
            outp[(size_t)(2 * t + 1) * NCOL] = lo + hi;
        }
        outp += (size_t)8 * NCOL;
    }

    // ---- fix l = L-1: reference zero-pads the win row at t=L, so the j=2
    // taps vanish there (not plain x zero-extension). ----
    if (l0 + TL == LL) {
        float s = 0.0f;
        #pragma unroll
        for (int i = 0; i < 8; i++) {
            #pragma unroll
            for (int j = 0; j < 2; j++) {
                s += ks[k * 24 + i * 3 + j] * rowA[TL + 20 + j - 3 * i];
            }
        }
        out[((size_t)(b * LL + LL - 1)) * NCOL + col] = s;
    }
}

extern "C" void kernel_launch(void* const* d_in, const int* in_sizes, int n_in,
                              void* d_out, int out_size) {
    const float* x    = (const float*)d_in[0];
    const float* kern = (const float*)d_in[1];
    float* out        = (float*)d_out;
    dim3 grid(LL / TL, BB);
    rocket_conv_kernel<<<grid, NCOL>>>(x, kern, out);
}